// round 1
// baseline (speedup 1.0000x reference)
#include <cuda_runtime.h>
#include <math.h>

#define Bsz 2
#define Ssz 2048
#define HIDs 2048
#define Hh 16
#define KVh 8
#define Dh 128

// ---------------- scratch (static device arrays: no allocs allowed) ----------
__device__ float g_q[(size_t)Bsz * Ssz * Hh * Dh];    // [B,S,H,D]
__device__ float g_k[(size_t)Bsz * Ssz * KVh * Dh];   // [B,S,KV,D]
__device__ float g_v[(size_t)Bsz * Ssz * KVh * Dh];   // [B,S,KV,D]
__device__ float g_att[(size_t)Bsz * Ssz * Hh * Dh];  // [B,S,H*D]

// ---------------- SGEMM: C[M,N] = A[M,K] @ B[K,N], all row-major fp32 --------
// 128x128 tile, BK=8, 256 threads, 8x8 microtile, register-prefetch pipeline.
__global__ __launch_bounds__(256) void sgemm_k(
    const float* __restrict__ A, const float* __restrict__ B,
    float* __restrict__ C, int M, int N, int K)
{
    __shared__ float As[8][128];   // transposed A tile: As[k][m]
    __shared__ float Bs[8][128];   // Bs[k][n]

    const int tid  = threadIdx.x;
    const int bm   = blockIdx.y * 128;
    const int bn   = blockIdx.x * 128;
    const int arow = tid >> 1;            // 0..127
    const int acol = (tid & 1) << 2;      // 0 or 4
    const int brow = tid >> 5;            // 0..7
    const int bcol = (tid & 31) << 2;     // 0..124
    const int ty   = tid >> 4;            // 0..15
    const int tx   = tid & 15;            // 0..15

    const float* Ap = A + (size_t)(bm + arow) * K + acol;
    const float* Bp = B + (size_t)brow * N + bn + bcol;

    float4 pa = *(const float4*)Ap;
    float4 pb = *(const float4*)Bp;

    float acc[8][8] = {};

    const int nk = K >> 3;
    for (int t = 0; t < nk; ++t) {
        As[acol + 0][arow] = pa.x;
        As[acol + 1][arow] = pa.y;
        As[acol + 2][arow] = pa.z;
        As[acol + 3][arow] = pa.w;
        *(float4*)&Bs[brow][bcol] = pb;
        __syncthreads();

        if (t + 1 < nk) {
            pa = *(const float4*)(Ap + (t + 1) * 8);
            pb = *(const float4*)(Bp + (size_t)(t + 1) * 8 * N);
        }

        #pragma unroll
        for (int kk = 0; kk < 8; ++kk) {
            float4 a0 = *(const float4*)&As[kk][ty << 2];
            float4 a1 = *(const float4*)&As[kk][(ty << 2) + 64];
            float4 b0 = *(const float4*)&Bs[kk][tx << 2];
            float4 b1 = *(const float4*)&Bs[kk][(tx << 2) + 64];
            float av[8] = {a0.x, a0.y, a0.z, a0.w, a1.x, a1.y, a1.z, a1.w};
            float bv[8] = {b0.x, b0.y, b0.z, b0.w, b1.x, b1.y, b1.z, b1.w};
            #pragma unroll
            for (int i = 0; i < 8; ++i)
                #pragma unroll
                for (int j = 0; j < 8; ++j)
                    acc[i][j] = fmaf(av[i], bv[j], acc[i][j]);
        }
        __syncthreads();
    }

    #pragma unroll
    for (int i = 0; i < 8; ++i) {
        int row = bm + (ty << 2) + (i < 4 ? i : 60 + i);
        float4 c0 = make_float4(acc[i][0], acc[i][1], acc[i][2], acc[i][3]);
        float4 c1 = make_float4(acc[i][4], acc[i][5], acc[i][6], acc[i][7]);
        *(float4*)&C[(size_t)row * N + bn + (tx << 2)]      = c0;
        *(float4*)&C[(size_t)row * N + bn + 64 + (tx << 2)] = c1;
    }
}

// ---------------- RMSNorm + RoPE (in place), one warp per (token, head) ------
__global__ __launch_bounds__(256) void norm_rope_k(
    float* __restrict__ t, const float* __restrict__ w,
    const float* __restrict__ cs, const float* __restrict__ sn, int nh)
{
    const int warp = blockIdx.x * 8 + (threadIdx.x >> 5);
    const int lane = threadIdx.x & 31;
    const int s = (warp / nh) % Ssz;

    float* row = t + (size_t)warp * Dh;
    float v0 = row[lane];
    float v1 = row[lane + 32];
    float v2 = row[lane + 64];
    float v3 = row[lane + 96];

    float ss = v0 * v0 + v1 * v1 + v2 * v2 + v3 * v3;
    #pragma unroll
    for (int o = 16; o; o >>= 1) ss += __shfl_xor_sync(0xffffffffu, ss, o);
    float r = rsqrtf(ss * (1.0f / 128.0f) + 1e-6f);

    v0 = v0 * r * w[lane];
    v1 = v1 * r * w[lane + 32];
    v2 = v2 * r * w[lane + 64];
    v3 = v3 * r * w[lane + 96];

    const float* cr = cs + (size_t)s * Dh;
    const float* sr = sn + (size_t)s * Dh;
    float o0 = v0 * cr[lane]      - v2 * sr[lane];
    float o1 = v1 * cr[lane + 32] - v3 * sr[lane + 32];
    float o2 = v2 * cr[lane + 64] + v0 * sr[lane + 64];
    float o3 = v3 * cr[lane + 96] + v1 * sr[lane + 96];

    row[lane]      = o0;
    row[lane + 32] = o1;
    row[lane + 64] = o2;
    row[lane + 96] = o3;
}

// ---------------- fp32 flash attention, causal, GQA --------------------------
// 64x64 tiles, D=128. 256 threads as 16(ty) x 16(tx).
// Score microtile: m = ty+16i (i<4), n = tx+16j (j<4).
// Output microtile: m = ty+16i, d = tx*4..+3 and tx*4+64..+67.
#define FPAD 132
#define PPAD 68
#define FLASH_SMEM ((64 * FPAD * 2 + 64 * PPAD) * 4)

__device__ __forceinline__ float dot4acc(float4 a, float4 b, float c) {
    c = fmaf(a.x, b.x, c);
    c = fmaf(a.y, b.y, c);
    c = fmaf(a.z, b.z, c);
    return fmaf(a.w, b.w, c);
}

__global__ __launch_bounds__(256, 2) void flash_k(
    const float* __restrict__ q, const float* __restrict__ k,
    const float* __restrict__ v, float* __restrict__ out)
{
    extern __shared__ float sm[];
    float* sQ  = sm;                  // [64][FPAD]
    float* sKV = sm + 64 * FPAD;      // [64][FPAD], K tile then V tile
    float* sP  = sm + 2 * 64 * FPAD;  // [64][PPAD]

    const int tid = threadIdx.x;
    const int ty = tid >> 4, tx = tid & 15;
    const int qb = gridDim.x - 1 - blockIdx.x;   // big blocks scheduled first
    const int h = blockIdx.y, b = blockIdx.z;
    const int kvh = h >> 1;                      // NREP = 2
    const int mBase = qb << 6;
    const float scale = 0.08838834764831845f;    // 1/sqrt(128)

    // load Q tile (rows m, gmem row stride H*D)
    const float* qp = q + (size_t)(b * Ssz + mBase) * (Hh * Dh) + h * Dh;
    #pragma unroll
    for (int it = 0; it < 8; ++it) {
        int ch = tid + (it << 8);
        int r = ch >> 5, c = (ch & 31) << 2;
        *(float4*)&sQ[r * FPAD + c] = *(const float4*)(qp + (size_t)r * (Hh * Dh) + c);
    }

    float o[4][8] = {};
    float mst[4], l[4];
    #pragma unroll
    for (int i = 0; i < 4; ++i) { mst[i] = -1e30f; l[i] = 0.0f; }

    for (int t = 0; t <= qb; ++t) {
        const int nBase = t << 6;
        __syncthreads();   // prev PV done before overwriting sKV

        const float* kp = k + (size_t)(b * Ssz + nBase) * (KVh * Dh) + kvh * Dh;
        #pragma unroll
        for (int it = 0; it < 8; ++it) {
            int ch = tid + (it << 8);
            int r = ch >> 5, c = (ch & 31) << 2;
            *(float4*)&sKV[r * FPAD + c] = *(const float4*)(kp + (size_t)r * (KVh * Dh) + c);
        }
        __syncthreads();

        // ---- scores S = Q K^T ----
        float acc[4][4] = {};
        #pragma unroll 4
        for (int d0 = 0; d0 < 128; d0 += 4) {
            float4 aF[4], bF[4];
            #pragma unroll
            for (int i = 0; i < 4; ++i)
                aF[i] = *(const float4*)&sQ[(ty + (i << 4)) * FPAD + d0];
            #pragma unroll
            for (int j = 0; j < 4; ++j)
                bF[j] = *(const float4*)&sKV[(tx + (j << 4)) * FPAD + d0];
            #pragma unroll
            for (int i = 0; i < 4; ++i)
                #pragma unroll
                for (int j = 0; j < 4; ++j)
                    acc[i][j] = dot4acc(aF[i], bF[j], acc[i][j]);
        }

        // ---- mask + online softmax ----
        #pragma unroll
        for (int i = 0; i < 4; ++i) {
            int gm = mBase + ty + (i << 4);
            float rm = -1e30f;
            #pragma unroll
            for (int j = 0; j < 4; ++j) {
                int gn = nBase + tx + (j << 4);
                float sv = (gn <= gm) ? acc[i][j] * scale : -1e30f;
                acc[i][j] = sv;
                rm = fmaxf(rm, sv);
            }
            rm = fmaxf(rm, __shfl_xor_sync(0xffffffffu, rm, 1));
            rm = fmaxf(rm, __shfl_xor_sync(0xffffffffu, rm, 2));
            rm = fmaxf(rm, __shfl_xor_sync(0xffffffffu, rm, 4));
            rm = fmaxf(rm, __shfl_xor_sync(0xffffffffu, rm, 8));

            float newm = fmaxf(mst[i], rm);
            float alpha = __expf(mst[i] - newm);
            mst[i] = newm;

            float rs = 0.0f;
            #pragma unroll
            for (int j = 0; j < 4; ++j) {
                float p = __expf(acc[i][j] - newm);
                acc[i][j] = p;
                rs += p;
            }
            rs += __shfl_xor_sync(0xffffffffu, rs, 1);
            rs += __shfl_xor_sync(0xffffffffu, rs, 2);
            rs += __shfl_xor_sync(0xffffffffu, rs, 4);
            rs += __shfl_xor_sync(0xffffffffu, rs, 8);

            l[i] = l[i] * alpha + rs;
            #pragma unroll
            for (int d = 0; d < 8; ++d) o[i][d] *= alpha;
            #pragma unroll
            for (int j = 0; j < 4; ++j)
                sP[(ty + (i << 4)) * PPAD + tx + (j << 4)] = acc[i][j];
        }
        __syncthreads();   // scores done reading sKV; sP fully written

        // ---- load V tile into sKV ----
        const float* vp = v + (size_t)(b * Ssz + nBase) * (KVh * Dh) + kvh * Dh;
        #pragma unroll
        for (int it = 0; it < 8; ++it) {
            int ch = tid + (it << 8);
            int r = ch >> 5, c = (ch & 31) << 2;
            *(float4*)&sKV[r * FPAD + c] = *(const float4*)(vp + (size_t)r * (KVh * Dh) + c);
        }
        __syncthreads();

        // ---- O += P V ----
        #pragma unroll 2
        for (int n = 0; n < 64; ++n) {
            float4 b0 = *(const float4*)&sKV[n * FPAD + (tx << 2)];
            float4 b1 = *(const float4*)&sKV[n * FPAD + (tx << 2) + 64];
            #pragma unroll
            for (int i = 0; i < 4; ++i) {
                float p = sP[(ty + (i << 4)) * PPAD + n];
                o[i][0] = fmaf(p, b0.x, o[i][0]);
                o[i][1] = fmaf(p, b0.y, o[i][1]);
                o[i][2] = fmaf(p, b0.z, o[i][2]);
                o[i][3] = fmaf(p, b0.w, o[i][3]);
                o[i][4] = fmaf(p, b1.x, o[i][4]);
                o[i][5] = fmaf(p, b1.y, o[i][5]);
                o[i][6] = fmaf(p, b1.z, o[i][6]);
                o[i][7] = fmaf(p, b1.w, o[i][7]);
            }
        }
    }

    // ---- epilogue ----
    #pragma unroll
    for (int i = 0; i < 4; ++i) {
        float inv = 1.0f / l[i];
        int gm = mBase + ty + (i << 4);
        float* op = out + ((size_t)(b * Ssz + gm) * Hh + h) * Dh;
        float4 c0 = make_float4(o[i][0] * inv, o[i][1] * inv, o[i][2] * inv, o[i][3] * inv);
        float4 c1 = make_float4(o[i][4] * inv, o[i][5] * inv, o[i][6] * inv, o[i][7] * inv);
        *(float4*)&op[tx << 2]        = c0;
        *(float4*)&op[(tx << 2) + 64] = c1;
    }
}

// ---------------- host launch -------------------------------------------------
extern "C" void kernel_launch(void* const* d_in, const int* in_sizes, int n_in,
                              void* d_out, int out_size)
{
    const float* x   = (const float*)d_in[0];
    const float* Wq  = (const float*)d_in[1];
    const float* Wk  = (const float*)d_in[2];
    const float* Wv  = (const float*)d_in[3];
    const float* Wo  = (const float*)d_in[4];
    const float* qnw = (const float*)d_in[5];
    const float* knw = (const float*)d_in[6];
    const float* cs  = (const float*)d_in[7];
    const float* sn  = (const float*)d_in[8];

    float *qb, *kb, *vb, *ab;
    cudaGetSymbolAddress((void**)&qb, g_q);
    cudaGetSymbolAddress((void**)&kb, g_k);
    cudaGetSymbolAddress((void**)&vb, g_v);
    cudaGetSymbolAddress((void**)&ab, g_att);

    const int M = Bsz * Ssz;   // 4096

    // QKV projections
    sgemm_k<<<dim3(HIDs / 128, M / 128), 256>>>(x, Wq, qb, M, Hh * Dh, HIDs);
    sgemm_k<<<dim3((KVh * Dh) / 128, M / 128), 256>>>(x, Wk, kb, M, KVh * Dh, HIDs);
    sgemm_k<<<dim3((KVh * Dh) / 128, M / 128), 256>>>(x, Wv, vb, M, KVh * Dh, HIDs);

    // RMSNorm + RoPE (in place)
    norm_rope_k<<<(Bsz * Ssz * Hh) / 8, 256>>>(qb, qnw, cs, sn, Hh);
    norm_rope_k<<<(Bsz * Ssz * KVh) / 8, 256>>>(kb, knw, cs, sn, KVh);

    // flash attention
    cudaFuncSetAttribute(flash_k, cudaFuncAttributeMaxDynamicSharedMemorySize, FLASH_SMEM);
    flash_k<<<dim3(Ssz / 64, Hh, Bsz), 256, FLASH_SMEM>>>(qb, kb, vb, ab);

    // output projection
    sgemm_k<<<dim3(HIDs / 128, M / 128), 256>>>(ab, Wo, (float*)d_out, M, HIDs, HIDs);
}

// round 3
// speedup vs baseline: 1.4086x; 1.4086x over previous
#include <cuda_runtime.h>
#include <cuda_bf16.h>
#include <math.h>

#define Bsz 2
#define Ssz 2048
#define HIDs 2048
#define Hh 16
#define KVh 8
#define Dh 128
#define KP 6144              // K' = 3*2048 for bf16x3 split
#define NT 96                // KP / 64 k-chunks
#define RSTR 72              // smem row stride in bf16 (144 B, conflict-free)
#define STG_A (128 * RSTR * 2)          // 18432 B per A tile
#define STG_BYTES (2 * STG_A)           // A + B per stage = 36864
#define GEMM_SMEM (2 * STG_BYTES)       // 2 stages = 73728

// ---------------- scratch (static device arrays: no allocs allowed) ----------
__device__ float g_q[(size_t)Bsz * Ssz * Hh * Dh];
__device__ float g_k[(size_t)Bsz * Ssz * KVh * Dh];
__device__ float g_v[(size_t)Bsz * Ssz * KVh * Dh];
__device__ float g_att[(size_t)Bsz * Ssz * Hh * Dh];

__device__ __align__(16) __nv_bfloat16 g_xp[(size_t)4096 * KP];
__device__ __align__(16) __nv_bfloat16 g_ap[(size_t)4096 * KP];
__device__ __align__(16) __nv_bfloat16 g_wqt[(size_t)2048 * KP];
__device__ __align__(16) __nv_bfloat16 g_wkt[(size_t)1024 * KP];
__device__ __align__(16) __nv_bfloat16 g_wvt[(size_t)1024 * KP];
__device__ __align__(16) __nv_bfloat16 g_wot[(size_t)2048 * KP];

// ====================== PTX helpers =========================================
__device__ __forceinline__ unsigned smem_u32(const void* p) {
    unsigned a;
    asm("{ .reg .u64 t; cvta.to.shared.u64 t, %1; cvt.u32.u64 %0, t; }"
        : "=r"(a) : "l"(p));
    return a;
}
#define CP16(dst, src) \
    asm volatile("cp.async.cg.shared.global [%0], [%1], 16;" :: "r"(dst), "l"(src))
#define CP_COMMIT() asm volatile("cp.async.commit_group;")

__device__ __forceinline__ void ldsm4(unsigned& r0, unsigned& r1,
                                      unsigned& r2, unsigned& r3, unsigned a) {
    asm volatile("ldmatrix.sync.aligned.m8n8.x4.shared.b16 {%0,%1,%2,%3}, [%4];"
                 : "=r"(r0), "=r"(r1), "=r"(r2), "=r"(r3) : "r"(a));
}
__device__ __forceinline__ void mma16816(float* d, const unsigned* a,
                                         unsigned b0, unsigned b1) {
    asm volatile(
        "mma.sync.aligned.m16n8k16.row.col.f32.bf16.bf16.f32 "
        "{%0,%1,%2,%3}, {%4,%5,%6,%7}, {%8,%9}, {%0,%1,%2,%3};"
        : "+f"(d[0]), "+f"(d[1]), "+f"(d[2]), "+f"(d[3])
        : "r"(a[0]), "r"(a[1]), "r"(a[2]), "r"(a[3]), "r"(b0), "r"(b1));
}

// ====================== conversion kernels ==================================
// A' = [hi | lo | hi] along K'   (src [M, 2048] fp32 row-major)
__global__ __launch_bounds__(256) void conv_a(
    const float* __restrict__ src, __nv_bfloat16* __restrict__ dst)
{
    size_t i = (size_t)blockIdx.x * 256 + threadIdx.x;
    int m = (int)(i >> 9);
    int k4 = (int)(i & 511);
    float4 v = ((const float4*)(src + (size_t)m * 2048))[k4];
    __nv_bfloat16 h0 = __float2bfloat16(v.x), h1 = __float2bfloat16(v.y);
    __nv_bfloat16 h2 = __float2bfloat16(v.z), h3 = __float2bfloat16(v.w);
    __nv_bfloat16 l0 = __float2bfloat16(v.x - __bfloat162float(h0));
    __nv_bfloat16 l1 = __float2bfloat16(v.y - __bfloat162float(h1));
    __nv_bfloat16 l2 = __float2bfloat16(v.z - __bfloat162float(h2));
    __nv_bfloat16 l3 = __float2bfloat16(v.w - __bfloat162float(h3));
    __nv_bfloat162 hA = __nv_bfloat162(h0, h1), hB = __nv_bfloat162(h2, h3);
    __nv_bfloat162 lA = __nv_bfloat162(l0, l1), lB = __nv_bfloat162(l2, l3);
    __nv_bfloat162* row = (__nv_bfloat162*)(dst + (size_t)m * KP) + k4 * 2;
    row[0] = hA; row[1] = hB;           // hi at k
    row[1024] = lA; row[1025] = lB;     // lo at K + k
    row[2048] = hA; row[2049] = hB;     // hi at 2K + k
}

// B' = W^T split: [n,k]=hi, [n,K+k]=hi, [n,2K+k]=lo.  W is [2048, N] fp32.
__global__ __launch_bounds__(256) void conv_w(
    const float* __restrict__ W, __nv_bfloat16* __restrict__ Bt, int N)
{
    __shared__ float ts[32][33];
    int n0 = blockIdx.x * 32, k0 = blockIdx.y * 32;
    int tx = threadIdx.x & 31, ty = threadIdx.x >> 5;
    #pragma unroll
    for (int r = 0; r < 4; ++r)
        ts[ty + r * 8][tx] = W[(size_t)(k0 + ty + r * 8) * N + n0 + tx];
    __syncthreads();
    #pragma unroll
    for (int r = 0; r < 4; ++r) {
        int n = n0 + ty + r * 8, k = k0 + tx;
        float v = ts[tx][ty + r * 8];
        __nv_bfloat16 hi = __float2bfloat16(v);
        __nv_bfloat16 lo = __float2bfloat16(v - __bfloat162float(hi));
        __nv_bfloat16* row = Bt + (size_t)n * KP;
        row[k] = hi; row[2048 + k] = hi; row[4096 + k] = lo;
    }
}

// ====================== HMMA bf16 GEMM ======================================
// C[M,N] fp32 = A'[M,K'] x B'[N,K'], both K-major bf16.
// 256 thr / 8 warps; CTA 128x128; warp 32x64; BK=64; double-buffered cp.async.
__global__ __launch_bounds__(256, 2) void gemm_mma(
    const __nv_bfloat16* __restrict__ A, const __nv_bfloat16* __restrict__ Bm,
    float* __restrict__ C, int N)
{
    extern __shared__ __align__(16) char smem[];
    const unsigned sb = smem_u32(smem);
    const int tid = threadIdx.x;
    const int lane = tid & 31;
    const int wid = tid >> 5;
    const int wr = wid >> 1;      // warp row 0..3 -> m offset 32*wr
    const int wc = wid & 1;       // warp col 0..1 -> n offset 64*wc
    const int bm = blockIdx.y << 7, bn = blockIdx.x << 7;

    // gmem load pointers: thread covers rows (tid>>3)+32i, 16B chunk (tid&7)
    const int lrow = tid >> 3, lcol = tid & 7;
    const __nv_bfloat16* Ag = A + (size_t)(bm + lrow) * KP + lcol * 8;
    const __nv_bfloat16* Bg = Bm + (size_t)(bn + lrow) * KP + lcol * 8;
    const unsigned sOff = lrow * 144 + lcol * 16;

    float acc[2][8][4];
    #pragma unroll
    for (int i = 0; i < 2; ++i)
        #pragma unroll
        for (int j = 0; j < 8; ++j)
            #pragma unroll
            for (int e = 0; e < 4; ++e) acc[i][j][e] = 0.0f;

    // ldmatrix base addresses (per lane)
    const unsigned aBase0 = sb + (32 * wr + (lane & 15)) * 144 + (lane >> 4) * 16;
    const unsigned bBase0 = sb + STG_A + (64 * wc + (lane & 15)) * 144 + (lane >> 4) * 16;

    // prologue: stage 0
    {
        const unsigned as = sb + sOff, bs = sb + STG_A + sOff;
        #pragma unroll
        for (int i = 0; i < 4; ++i) {
            CP16(as + i * 32 * 144, Ag + (size_t)(32 * i) * KP);
            CP16(bs + i * 32 * 144, Bg + (size_t)(32 * i) * KP);
        }
        CP_COMMIT();
    }

    for (int c = 0; c < NT; ++c) {
        if (c + 1 < NT) {
            const unsigned st = ((c + 1) & 1) * STG_BYTES;
            const unsigned as = sb + st + sOff, bs = sb + st + STG_A + sOff;
            const __nv_bfloat16* ag = Ag + (size_t)(c + 1) * 64;
            const __nv_bfloat16* bg = Bg + (size_t)(c + 1) * 64;
            #pragma unroll
            for (int i = 0; i < 4; ++i) {
                CP16(as + i * 32 * 144, ag + (size_t)(32 * i) * KP);
                CP16(bs + i * 32 * 144, bg + (size_t)(32 * i) * KP);
            }
            CP_COMMIT();
            asm volatile("cp.async.wait_group 1;" ::: "memory");
        } else {
            asm volatile("cp.async.wait_group 0;" ::: "memory");
        }
        __syncthreads();

        const unsigned st = (c & 1) * STG_BYTES;
        const unsigned aB = aBase0 + st, bB = bBase0 + st;
        #pragma unroll
        for (int ks = 0; ks < 4; ++ks) {
            unsigned a[2][4];
            ldsm4(a[0][0], a[0][1], a[0][2], a[0][3], aB + ks * 32);
            ldsm4(a[1][0], a[1][1], a[1][2], a[1][3], aB + 16 * 144 + ks * 32);
            unsigned b[8][2];
            #pragma unroll
            for (int nt = 0; nt < 4; ++nt) {
                unsigned r0, r1, r2, r3;
                ldsm4(r0, r1, r2, r3, bB + nt * 16 * 144 + ks * 32);
                b[nt * 2][0] = r0; b[nt * 2][1] = r2;
                b[nt * 2 + 1][0] = r1; b[nt * 2 + 1][1] = r3;
            }
            #pragma unroll
            for (int mt = 0; mt < 2; ++mt)
                #pragma unroll
                for (int nt = 0; nt < 8; ++nt)
                    mma16816(acc[mt][nt], a[mt], b[nt][0], b[nt][1]);
        }
        __syncthreads();
    }

    // epilogue
    #pragma unroll
    for (int mt = 0; mt < 2; ++mt) {
        const int r0 = bm + 32 * wr + 16 * mt + (lane >> 2);
        #pragma unroll
        for (int nt = 0; nt < 8; ++nt) {
            const int col = bn + 64 * wc + 8 * nt + (lane & 3) * 2;
            float2 v0 = make_float2(acc[mt][nt][0], acc[mt][nt][1]);
            float2 v1 = make_float2(acc[mt][nt][2], acc[mt][nt][3]);
            *(float2*)&C[(size_t)r0 * N + col]       = v0;
            *(float2*)&C[(size_t)(r0 + 8) * N + col] = v1;
        }
    }
}

// ---------------- RMSNorm + RoPE (in place), one warp per (token, head) ------
__global__ __launch_bounds__(256) void norm_rope_k(
    float* __restrict__ t, const float* __restrict__ w,
    const float* __restrict__ cs, const float* __restrict__ sn, int nh)
{
    const int warp = blockIdx.x * 8 + (threadIdx.x >> 5);
    const int lane = threadIdx.x & 31;
    const int s = (warp / nh) % Ssz;

    float* row = t + (size_t)warp * Dh;
    float v0 = row[lane];
    float v1 = row[lane + 32];
    float v2 = row[lane + 64];
    float v3 = row[lane + 96];

    float ss = v0 * v0 + v1 * v1 + v2 * v2 + v3 * v3;
    #pragma unroll
    for (int o = 16; o; o >>= 1) ss += __shfl_xor_sync(0xffffffffu, ss, o);
    float r = rsqrtf(ss * (1.0f / 128.0f) + 1e-6f);

    v0 = v0 * r * w[lane];
    v1 = v1 * r * w[lane + 32];
    v2 = v2 * r * w[lane + 64];
    v3 = v3 * r * w[lane + 96];

    const float* cr = cs + (size_t)s * Dh;
    const float* sr = sn + (size_t)s * Dh;
    float o0 = v0 * cr[lane]      - v2 * sr[lane];
    float o1 = v1 * cr[lane + 32] - v3 * sr[lane + 32];
    float o2 = v2 * cr[lane + 64] + v0 * sr[lane + 64];
    float o3 = v3 * cr[lane + 96] + v1 * sr[lane + 96];

    row[lane]      = o0;
    row[lane + 32] = o1;
    row[lane + 64] = o2;
    row[lane + 96] = o3;
}

// ---------------- fp32 flash attention, causal, GQA --------------------------
#define FPAD 132
#define PPAD 68
#define FLASH_SMEM ((64 * FPAD * 2 + 64 * PPAD) * 4)

__device__ __forceinline__ float dot4acc(float4 a, float4 b, float c) {
    c = fmaf(a.x, b.x, c);
    c = fmaf(a.y, b.y, c);
    c = fmaf(a.z, b.z, c);
    return fmaf(a.w, b.w, c);
}

__global__ __launch_bounds__(256, 2) void flash_k(
    const float* __restrict__ q, const float* __restrict__ k,
    const float* __restrict__ v, float* __restrict__ out)
{
    extern __shared__ float sm[];
    float* sQ  = sm;
    float* sKV = sm + 64 * FPAD;
    float* sP  = sm + 2 * 64 * FPAD;

    const int tid = threadIdx.x;
    const int ty = tid >> 4, tx = tid & 15;
    const int qb = gridDim.x - 1 - blockIdx.x;
    const int h = blockIdx.y, b = blockIdx.z;
    const int kvh = h >> 1;
    const int mBase = qb << 6;
    const float scale = 0.08838834764831845f;

    const float* qp = q + (size_t)(b * Ssz + mBase) * (Hh * Dh) + h * Dh;
    #pragma unroll
    for (int it = 0; it < 8; ++it) {
        int ch = tid + (it << 8);
        int r = ch >> 5, c = (ch & 31) << 2;
        *(float4*)&sQ[r * FPAD + c] = *(const float4*)(qp + (size_t)r * (Hh * Dh) + c);
    }

    float o[4][8] = {};
    float mst[4], l[4];
    #pragma unroll
    for (int i = 0; i < 4; ++i) { mst[i] = -1e30f; l[i] = 0.0f; }

    for (int t = 0; t <= qb; ++t) {
        const int nBase = t << 6;
        __syncthreads();

        const float* kp = k + (size_t)(b * Ssz + nBase) * (KVh * Dh) + kvh * Dh;
        #pragma unroll
        for (int it = 0; it < 8; ++it) {
            int ch = tid + (it << 8);
            int r = ch >> 5, c = (ch & 31) << 2;
            *(float4*)&sKV[r * FPAD + c] = *(const float4*)(kp + (size_t)r * (KVh * Dh) + c);
        }
        __syncthreads();

        float acc[4][4] = {};
        #pragma unroll 4
        for (int d0 = 0; d0 < 128; d0 += 4) {
            float4 aF[4], bF[4];
            #pragma unroll
            for (int i = 0; i < 4; ++i)
                aF[i] = *(const float4*)&sQ[(ty + (i << 4)) * FPAD + d0];
            #pragma unroll
            for (int j = 0; j < 4; ++j)
                bF[j] = *(const float4*)&sKV[(tx + (j << 4)) * FPAD + d0];
            #pragma unroll
            for (int i = 0; i < 4; ++i)
                #pragma unroll
                for (int j = 0; j < 4; ++j)
                    acc[i][j] = dot4acc(aF[i], bF[j], acc[i][j]);
        }

        #pragma unroll
        for (int i = 0; i < 4; ++i) {
            int gm = mBase + ty + (i << 4);
            float rm = -1e30f;
            #pragma unroll
            for (int j = 0; j < 4; ++j) {
                int gn = nBase + tx + (j << 4);
                float sv = (gn <= gm) ? acc[i][j] * scale : -1e30f;
                acc[i][j] = sv;
                rm = fmaxf(rm, sv);
            }
            rm = fmaxf(rm, __shfl_xor_sync(0xffffffffu, rm, 1));
            rm = fmaxf(rm, __shfl_xor_sync(0xffffffffu, rm, 2));
            rm = fmaxf(rm, __shfl_xor_sync(0xffffffffu, rm, 4));
            rm = fmaxf(rm, __shfl_xor_sync(0xffffffffu, rm, 8));

            float newm = fmaxf(mst[i], rm);
            float alpha = __expf(mst[i] - newm);
            mst[i] = newm;

            float rs = 0.0f;
            #pragma unroll
            for (int j = 0; j < 4; ++j) {
                float p = __expf(acc[i][j] - newm);
                acc[i][j] = p;
                rs += p;
            }
            rs += __shfl_xor_sync(0xffffffffu, rs, 1);
            rs += __shfl_xor_sync(0xffffffffu, rs, 2);
            rs += __shfl_xor_sync(0xffffffffu, rs, 4);
            rs += __shfl_xor_sync(0xffffffffu, rs, 8);

            l[i] = l[i] * alpha + rs;
            #pragma unroll
            for (int d = 0; d < 8; ++d) o[i][d] *= alpha;
            #pragma unroll
            for (int j = 0; j < 4; ++j)
                sP[(ty + (i << 4)) * PPAD + tx + (j << 4)] = acc[i][j];
        }
        __syncthreads();

        const float* vp = v + (size_t)(b * Ssz + nBase) * (KVh * Dh) + kvh * Dh;
        #pragma unroll
        for (int it = 0; it < 8; ++it) {
            int ch = tid + (it << 8);
            int r = ch >> 5, c = (ch & 31) << 2;
            *(float4*)&sKV[r * FPAD + c] = *(const float4*)(vp + (size_t)r * (KVh * Dh) + c);
        }
        __syncthreads();

        #pragma unroll 2
        for (int n = 0; n < 64; ++n) {
            float4 b0 = *(const float4*)&sKV[n * FPAD + (tx << 2)];
            float4 b1 = *(const float4*)&sKV[n * FPAD + (tx << 2) + 64];
            #pragma unroll
            for (int i = 0; i < 4; ++i) {
                float p = sP[(ty + (i << 4)) * PPAD + n];
                o[i][0] = fmaf(p, b0.x, o[i][0]);
                o[i][1] = fmaf(p, b0.y, o[i][1]);
                o[i][2] = fmaf(p, b0.z, o[i][2]);
                o[i][3] = fmaf(p, b0.w, o[i][3]);
                o[i][4] = fmaf(p, b1.x, o[i][4]);
                o[i][5] = fmaf(p, b1.y, o[i][5]);
                o[i][6] = fmaf(p, b1.z, o[i][6]);
                o[i][7] = fmaf(p, b1.w, o[i][7]);
            }
        }
    }

    #pragma unroll
    for (int i = 0; i < 4; ++i) {
        float inv = 1.0f / l[i];
        int gm = mBase + ty + (i << 4);
        float* op = out + ((size_t)(b * Ssz + gm) * Hh + h) * Dh;
        float4 c0 = make_float4(o[i][0] * inv, o[i][1] * inv, o[i][2] * inv, o[i][3] * inv);
        float4 c1 = make_float4(o[i][4] * inv, o[i][5] * inv, o[i][6] * inv, o[i][7] * inv);
        *(float4*)&op[tx << 2]        = c0;
        *(float4*)&op[(tx << 2) + 64] = c1;
    }
}

// ---------------- host launch -------------------------------------------------
extern "C" void kernel_launch(void* const* d_in, const int* in_sizes, int n_in,
                              void* d_out, int out_size)
{
    const float* x   = (const float*)d_in[0];
    const float* Wq  = (const float*)d_in[1];
    const float* Wk  = (const float*)d_in[2];
    const float* Wv  = (const float*)d_in[3];
    const float* Wo  = (const float*)d_in[4];
    const float* qnw = (const float*)d_in[5];
    const float* knw = (const float*)d_in[6];
    const float* cs  = (const float*)d_in[7];
    const float* sn  = (const float*)d_in[8];

    float *qb, *kb, *vb, *ab;
    __nv_bfloat16 *xp, *ap, *wqt, *wkt, *wvt, *wot;
    cudaGetSymbolAddress((void**)&qb, g_q);
    cudaGetSymbolAddress((void**)&kb, g_k);
    cudaGetSymbolAddress((void**)&vb, g_v);
    cudaGetSymbolAddress((void**)&ab, g_att);
    cudaGetSymbolAddress((void**)&xp, g_xp);
    cudaGetSymbolAddress((void**)&ap, g_ap);
    cudaGetSymbolAddress((void**)&wqt, g_wqt);
    cudaGetSymbolAddress((void**)&wkt, g_wkt);
    cudaGetSymbolAddress((void**)&wvt, g_wvt);
    cudaGetSymbolAddress((void**)&wot, g_wot);

    cudaFuncSetAttribute(gemm_mma, cudaFuncAttributeMaxDynamicSharedMemorySize, GEMM_SMEM);
    cudaFuncSetAttribute(flash_k, cudaFuncAttributeMaxDynamicSharedMemorySize, FLASH_SMEM);

    // split/convert inputs + weights
    conv_a<<<8192, 256>>>(x, xp);
    conv_w<<<dim3(64, 64), 256>>>(Wq, wqt, 2048);
    conv_w<<<dim3(32, 64), 256>>>(Wk, wkt, 1024);
    conv_w<<<dim3(32, 64), 256>>>(Wv, wvt, 1024);
    conv_w<<<dim3(64, 64), 256>>>(Wo, wot, 2048);

    // QKV projections on tensor cores (bf16x3, HMMA)
    gemm_mma<<<dim3(16, 32), 256, GEMM_SMEM>>>(xp, wqt, qb, 2048);
    gemm_mma<<<dim3(8, 32), 256, GEMM_SMEM>>>(xp, wkt, kb, 1024);
    gemm_mma<<<dim3(8, 32), 256, GEMM_SMEM>>>(xp, wvt, vb, 1024);

    // RMSNorm + RoPE
    norm_rope_k<<<(Bsz * Ssz * Hh) / 8, 256>>>(qb, qnw, cs, sn, Hh);
    norm_rope_k<<<(Bsz * Ssz * KVh) / 8, 256>>>(kb, knw, cs, sn, KVh);

    // flash attention (fp32)
    flash_k<<<dim3(Ssz / 64, Hh, Bsz), 256, FLASH_SMEM>>>(qb, kb, vb, ab);

    // output projection
    conv_a<<<8192, 256>>>(ab, ap);
    gemm_mma<<<dim3(16, 32), 256, GEMM_SMEM>>>(ap, wot, (float*)d_out, 2048);
}

// round 5
// speedup vs baseline: 1.8906x; 1.3421x over previous
#include <cuda_runtime.h>
#include <cuda_bf16.h>
#include <math.h>

#define Bsz 2
#define Ssz 2048
#define HIDs 2048
#define Hh 16
#define KVh 8
#define Dh 128
#define KP 6144              // K' = 3*2048 for bf16x3 split
#define NT 96                // KP / 64 k-chunks
#define STG_A (128 * 72 * 2)            // 18432 B per A tile (stride 144B)
#define STG_BYTES (2 * STG_A)
#define GEMM_SMEM (2 * STG_BYTES)

// flash smem layout (per stage): Kh[64][136], Kl[64][136], Vth[128][72], Vtl[128][72]
#define FL_STAGE 71680
#define FL_SMEM (2 * FL_STAGE)          // 143360

// ---------------- scratch (static device arrays: no allocs allowed) ----------
__device__ float g_q[(size_t)Bsz * Ssz * Hh * Dh];
__device__ float g_k[(size_t)Bsz * Ssz * KVh * Dh];
__device__ float g_v[(size_t)Bsz * Ssz * KVh * Dh];
__device__ float g_att[(size_t)Bsz * Ssz * Hh * Dh];

__device__ __align__(16) __nv_bfloat16 g_xp[(size_t)4096 * KP];
__device__ __align__(16) __nv_bfloat16 g_ap[(size_t)4096 * KP];
__device__ __align__(16) __nv_bfloat16 g_wqt[(size_t)2048 * KP];
__device__ __align__(16) __nv_bfloat16 g_wkt[(size_t)1024 * KP];
__device__ __align__(16) __nv_bfloat16 g_wvt[(size_t)1024 * KP];
__device__ __align__(16) __nv_bfloat16 g_wot[(size_t)2048 * KP];

// head-major bf16 splits for flash
__device__ __align__(16) __nv_bfloat16 g_qh[(size_t)Bsz * Hh * Ssz * Dh];
__device__ __align__(16) __nv_bfloat16 g_ql[(size_t)Bsz * Hh * Ssz * Dh];
__device__ __align__(16) __nv_bfloat16 g_kh[(size_t)Bsz * KVh * Ssz * Dh];
__device__ __align__(16) __nv_bfloat16 g_kl[(size_t)Bsz * KVh * Ssz * Dh];
__device__ __align__(16) __nv_bfloat16 g_vth[(size_t)Bsz * KVh * Dh * Ssz];
__device__ __align__(16) __nv_bfloat16 g_vtl[(size_t)Bsz * KVh * Dh * Ssz];

// ====================== PTX helpers =========================================
__device__ __forceinline__ unsigned smem_u32(const void* p) {
    unsigned a;
    asm("{ .reg .u64 t; cvta.to.shared.u64 t, %1; cvt.u32.u64 %0, t; }"
        : "=r"(a) : "l"(p));
    return a;
}
#define CP16(dst, src) \
    asm volatile("cp.async.cg.shared.global [%0], [%1], 16;" :: "r"(dst), "l"(src))
#define CP_COMMIT() asm volatile("cp.async.commit_group;")

__device__ __forceinline__ void ldsm4(unsigned& r0, unsigned& r1,
                                      unsigned& r2, unsigned& r3, unsigned a) {
    asm volatile("ldmatrix.sync.aligned.m8n8.x4.shared.b16 {%0,%1,%2,%3}, [%4];"
                 : "=r"(r0), "=r"(r1), "=r"(r2), "=r"(r3) : "r"(a));
}
__device__ __forceinline__ void mma16816(float* d, const unsigned* a,
                                         unsigned b0, unsigned b1) {
    asm volatile(
        "mma.sync.aligned.m16n8k16.row.col.f32.bf16.bf16.f32 "
        "{%0,%1,%2,%3}, {%4,%5,%6,%7}, {%8,%9}, {%0,%1,%2,%3};"
        : "+f"(d[0]), "+f"(d[1]), "+f"(d[2]), "+f"(d[3])
        : "r"(a[0]), "r"(a[1]), "r"(a[2]), "r"(a[3]), "r"(b0), "r"(b1));
}
__device__ __forceinline__ unsigned pack2(float lo, float hi) {
    unsigned d;
    asm("cvt.rn.bf16x2.f32 %0, %1, %2;" : "=r"(d) : "f"(hi), "f"(lo));
    return d;
}
__device__ __forceinline__ float bfres(float x) {
    return x - __bfloat162float(__float2bfloat16(x));
}

// ====================== conversion kernels ==================================
__global__ __launch_bounds__(256) void conv_a(
    const float* __restrict__ src, __nv_bfloat16* __restrict__ dst)
{
    size_t i = (size_t)blockIdx.x * 256 + threadIdx.x;
    int m = (int)(i >> 9);
    int k4 = (int)(i & 511);
    float4 v = ((const float4*)(src + (size_t)m * 2048))[k4];
    __nv_bfloat16 h0 = __float2bfloat16(v.x), h1 = __float2bfloat16(v.y);
    __nv_bfloat16 h2 = __float2bfloat16(v.z), h3 = __float2bfloat16(v.w);
    __nv_bfloat16 l0 = __float2bfloat16(v.x - __bfloat162float(h0));
    __nv_bfloat16 l1 = __float2bfloat16(v.y - __bfloat162float(h1));
    __nv_bfloat16 l2 = __float2bfloat16(v.z - __bfloat162float(h2));
    __nv_bfloat16 l3 = __float2bfloat16(v.w - __bfloat162float(h3));
    __nv_bfloat162 hA = __nv_bfloat162(h0, h1), hB = __nv_bfloat162(h2, h3);
    __nv_bfloat162 lA = __nv_bfloat162(l0, l1), lB = __nv_bfloat162(l2, l3);
    __nv_bfloat162* row = (__nv_bfloat162*)(dst + (size_t)m * KP) + k4 * 2;
    row[0] = hA; row[1] = hB;
    row[1024] = lA; row[1025] = lB;
    row[2048] = hA; row[2049] = hB;
}

__global__ __launch_bounds__(256) void conv_w(
    const float* __restrict__ W, __nv_bfloat16* __restrict__ Bt, int N)
{
    __shared__ float ts[32][33];
    int n0 = blockIdx.x * 32, k0 = blockIdx.y * 32;
    int tx = threadIdx.x & 31, ty = threadIdx.x >> 5;
    #pragma unroll
    for (int r = 0; r < 4; ++r)
        ts[ty + r * 8][tx] = W[(size_t)(k0 + ty + r * 8) * N + n0 + tx];
    __syncthreads();
    #pragma unroll
    for (int r = 0; r < 4; ++r) {
        int n = n0 + ty + r * 8, k = k0 + tx;
        float v = ts[tx][ty + r * 8];
        __nv_bfloat16 hi = __float2bfloat16(v);
        __nv_bfloat16 lo = __float2bfloat16(v - __bfloat162float(hi));
        __nv_bfloat16* row = Bt + (size_t)n * KP;
        row[k] = hi; row[2048 + k] = hi; row[4096 + k] = lo;
    }
}

// [B,S,nh,128] fp32 -> [B,nh,S,128] bf16 hi/lo (optionally scaled)
__global__ __launch_bounds__(256) void conv_qk(
    const float* __restrict__ src, __nv_bfloat16* __restrict__ dh,
    __nv_bfloat16* __restrict__ dl, int nh, float scale)
{
    size_t i = (size_t)blockIdx.x * 256 + threadIdx.x;   // over B*S*nh*32 f4
    int c4 = (int)(i & 31);
    size_t rest = i >> 5;
    int hh = (int)(rest % nh);
    size_t bs = rest / nh;                               // b*S + s
    float4 v = ((const float4*)src)[i];
    v.x *= scale; v.y *= scale; v.z *= scale; v.w *= scale;
    __nv_bfloat16 h0 = __float2bfloat16(v.x), h1 = __float2bfloat16(v.y);
    __nv_bfloat16 h2 = __float2bfloat16(v.z), h3 = __float2bfloat16(v.w);
    __nv_bfloat16 l0 = __float2bfloat16(v.x - __bfloat162float(h0));
    __nv_bfloat16 l1 = __float2bfloat16(v.y - __bfloat162float(h1));
    __nv_bfloat16 l2 = __float2bfloat16(v.z - __bfloat162float(h2));
    __nv_bfloat16 l3 = __float2bfloat16(v.w - __bfloat162float(h3));
    int s = (int)(bs % Ssz), b = (int)(bs / Ssz);
    size_t o = ((((size_t)b * nh + hh) * Ssz + s) * 128 + c4 * 4) >> 2;
    ((__nv_bfloat162*)dh)[o * 2] = __nv_bfloat162(h0, h1);
    ((__nv_bfloat162*)dh)[o * 2 + 1] = __nv_bfloat162(h2, h3);
    ((__nv_bfloat162*)dl)[o * 2] = __nv_bfloat162(l0, l1);
    ((__nv_bfloat162*)dl)[o * 2 + 1] = __nv_bfloat162(l2, l3);
}

// V [B,S,KV,128] fp32 -> Vt hi/lo [B*KV, 128, S] bf16
__global__ __launch_bounds__(256) void conv_vt(
    const float* __restrict__ v, __nv_bfloat16* __restrict__ th,
    __nv_bfloat16* __restrict__ tl)
{
    __shared__ float ts[32][33];
    int s0 = blockIdx.x * 32, d0 = blockIdx.y * 32;
    int bk = blockIdx.z;
    int b = bk >> 3, kv = bk & 7;
    int tx = threadIdx.x & 31, ty = threadIdx.x >> 5;
    #pragma unroll
    for (int r = 0; r < 4; ++r)
        ts[ty + r * 8][tx] =
            v[((size_t)(b * Ssz + s0 + ty + r * 8) * KVh + kv) * 128 + d0 + tx];
    __syncthreads();
    #pragma unroll
    for (int r = 0; r < 4; ++r) {
        float x = ts[tx][ty + r * 8];
        __nv_bfloat16 hi = __float2bfloat16(x);
        __nv_bfloat16 lo = __float2bfloat16(x - __bfloat162float(hi));
        size_t o = ((size_t)bk * 128 + d0 + ty + r * 8) * Ssz + s0 + tx;
        th[o] = hi; tl[o] = lo;
    }
}

// ====================== HMMA bf16 GEMM (unchanged from R3) ==================
__global__ __launch_bounds__(256, 2) void gemm_mma(
    const __nv_bfloat16* __restrict__ A, const __nv_bfloat16* __restrict__ Bm,
    float* __restrict__ C, int N)
{
    extern __shared__ __align__(16) char smem[];
    const unsigned sb = smem_u32(smem);
    const int tid = threadIdx.x;
    const int lane = tid & 31;
    const int wid = tid >> 5;
    const int wr = wid >> 1;
    const int wc = wid & 1;
    const int bm = blockIdx.y << 7, bn = blockIdx.x << 7;

    const int lrow = tid >> 3, lcol = tid & 7;
    const __nv_bfloat16* Ag = A + (size_t)(bm + lrow) * KP + lcol * 8;
    const __nv_bfloat16* Bg = Bm + (size_t)(bn + lrow) * KP + lcol * 8;
    const unsigned sOff = lrow * 144 + lcol * 16;

    float acc[2][8][4];
    #pragma unroll
    for (int i = 0; i < 2; ++i)
        #pragma unroll
        for (int j = 0; j < 8; ++j)
            #pragma unroll
            for (int e = 0; e < 4; ++e) acc[i][j][e] = 0.0f;

    const unsigned aBase0 = sb + (32 * wr + (lane & 15)) * 144 + (lane >> 4) * 16;
    const unsigned bBase0 = sb + STG_A + (64 * wc + (lane & 15)) * 144 + (lane >> 4) * 16;

    {
        const unsigned as = sb + sOff, bs = sb + STG_A + sOff;
        #pragma unroll
        for (int i = 0; i < 4; ++i) {
            CP16(as + i * 32 * 144, Ag + (size_t)(32 * i) * KP);
            CP16(bs + i * 32 * 144, Bg + (size_t)(32 * i) * KP);
        }
        CP_COMMIT();
    }

    for (int c = 0; c < NT; ++c) {
        if (c + 1 < NT) {
            const unsigned st = ((c + 1) & 1) * STG_BYTES;
            const unsigned as = sb + st + sOff, bs = sb + st + STG_A + sOff;
            const __nv_bfloat16* ag = Ag + (size_t)(c + 1) * 64;
            const __nv_bfloat16* bg = Bg + (size_t)(c + 1) * 64;
            #pragma unroll
            for (int i = 0; i < 4; ++i) {
                CP16(as + i * 32 * 144, ag + (size_t)(32 * i) * KP);
                CP16(bs + i * 32 * 144, bg + (size_t)(32 * i) * KP);
            }
            CP_COMMIT();
            asm volatile("cp.async.wait_group 1;" ::: "memory");
        } else {
            asm volatile("cp.async.wait_group 0;" ::: "memory");
        }
        __syncthreads();

        const unsigned st = (c & 1) * STG_BYTES;
        const unsigned aB = aBase0 + st, bB = bBase0 + st;
        #pragma unroll
        for (int ks = 0; ks < 4; ++ks) {
            unsigned a[2][4];
            ldsm4(a[0][0], a[0][1], a[0][2], a[0][3], aB + ks * 32);
            ldsm4(a[1][0], a[1][1], a[1][2], a[1][3], aB + 16 * 144 + ks * 32);
            unsigned b[8][2];
            #pragma unroll
            for (int nt = 0; nt < 4; ++nt) {
                unsigned r0, r1, r2, r3;
                ldsm4(r0, r1, r2, r3, bB + nt * 16 * 144 + ks * 32);
                b[nt * 2][0] = r0; b[nt * 2][1] = r2;
                b[nt * 2 + 1][0] = r1; b[nt * 2 + 1][1] = r3;
            }
            #pragma unroll
            for (int mt = 0; mt < 2; ++mt)
                #pragma unroll
                for (int nt = 0; nt < 8; ++nt)
                    mma16816(acc[mt][nt], a[mt], b[nt][0], b[nt][1]);
        }
        __syncthreads();
    }

    #pragma unroll
    for (int mt = 0; mt < 2; ++mt) {
        const int r0 = bm + 32 * wr + 16 * mt + (lane >> 2);
        #pragma unroll
        for (int nt = 0; nt < 8; ++nt) {
            const int col = bn + 64 * wc + 8 * nt + (lane & 3) * 2;
            float2 v0 = make_float2(acc[mt][nt][0], acc[mt][nt][1]);
            float2 v1 = make_float2(acc[mt][nt][2], acc[mt][nt][3]);
            *(float2*)&C[(size_t)r0 * N + col]       = v0;
            *(float2*)&C[(size_t)(r0 + 8) * N + col] = v1;
        }
    }
}

// ---------------- RMSNorm + RoPE (in place) ----------------------------------
__global__ __launch_bounds__(256) void norm_rope_k(
    float* __restrict__ t, const float* __restrict__ w,
    const float* __restrict__ cs, const float* __restrict__ sn, int nh)
{
    const int warp = blockIdx.x * 8 + (threadIdx.x >> 5);
    const int lane = threadIdx.x & 31;
    const int s = (warp / nh) % Ssz;

    float* row = t + (size_t)warp * Dh;
    float v0 = row[lane];
    float v1 = row[lane + 32];
    float v2 = row[lane + 64];
    float v3 = row[lane + 96];

    float ss = v0 * v0 + v1 * v1 + v2 * v2 + v3 * v3;
    #pragma unroll
    for (int o = 16; o; o >>= 1) ss += __shfl_xor_sync(0xffffffffu, ss, o);
    float r = rsqrtf(ss * (1.0f / 128.0f) + 1e-6f);

    v0 = v0 * r * w[lane];
    v1 = v1 * r * w[lane + 32];
    v2 = v2 * r * w[lane + 64];
    v3 = v3 * r * w[lane + 96];

    const float* cr = cs + (size_t)s * Dh;
    const float* sr = sn + (size_t)s * Dh;
    float o0 = v0 * cr[lane]      - v2 * sr[lane];
    float o1 = v1 * cr[lane + 32] - v3 * sr[lane + 32];
    float o2 = v2 * cr[lane + 64] + v0 * sr[lane + 64];
    float o3 = v3 * cr[lane + 96] + v1 * sr[lane + 96];

    row[lane]      = o0;
    row[lane + 32] = o1;
    row[lane + 64] = o2;
    row[lane + 96] = o3;
}

// ====================== HMMA flash attention ================================
__device__ __forceinline__ void load_kv_tile(
    unsigned sbase, int tid,
    const __nv_bfloat16* khp, const __nv_bfloat16* klp,
    const __nv_bfloat16* vthp, const __nv_bfloat16* vtlp, int nBase)
{
    const int r = tid >> 2, c0 = (tid & 3) * 4;
    const char* gk = (const char*)(khp + (size_t)(nBase + r) * 128) + c0 * 16;
    const char* gl = (const char*)(klp + (size_t)(nBase + r) * 128) + c0 * 16;
    const unsigned dk = sbase + r * 272 + c0 * 16;
    #pragma unroll
    for (int i = 0; i < 4; ++i) {
        CP16(dk + i * 16, gk + i * 16);
        CP16(dk + 17408 + i * 16, gl + i * 16);
    }
    const int r2 = tid >> 1, c2 = (tid & 1) * 4;
    const char* gv = (const char*)(vthp + (size_t)r2 * Ssz + nBase) + c2 * 16;
    const char* gw = (const char*)(vtlp + (size_t)r2 * Ssz + nBase) + c2 * 16;
    const unsigned dv = sbase + 34816 + r2 * 144 + c2 * 16;
    #pragma unroll
    for (int i = 0; i < 4; ++i) {
        CP16(dv + i * 16, gv + i * 16);
        CP16(dv + 18432 + i * 16, gw + i * 16);
    }
}

__global__ __launch_bounds__(256, 1) void flash_mma(
    const __nv_bfloat16* __restrict__ qh, const __nv_bfloat16* __restrict__ ql,
    const __nv_bfloat16* __restrict__ kh, const __nv_bfloat16* __restrict__ kl,
    const __nv_bfloat16* __restrict__ vth, const __nv_bfloat16* __restrict__ vtl,
    float* __restrict__ out)
{
    extern __shared__ __align__(16) char smem[];
    const unsigned sb = smem_u32(smem);
    const int tid = threadIdx.x, lane = tid & 31, w = tid >> 5;
    const int qi = 15 - blockIdx.x;
    const int h = blockIdx.y, b = blockIdx.z;
    const int kvh = h >> 1;
    const int mBase = qi << 7;
    const int ntiles = 2 * qi + 2;

    const __nv_bfloat16* qhp = qh + (((size_t)b * Hh + h) * Ssz + mBase) * Dh;
    const __nv_bfloat16* qlp = ql + (((size_t)b * Hh + h) * Ssz + mBase) * Dh;
    const __nv_bfloat16* khp = kh + ((size_t)b * KVh + kvh) * Ssz * Dh;
    const __nv_bfloat16* klp = kl + ((size_t)b * KVh + kvh) * Ssz * Dh;
    const __nv_bfloat16* vthp = vth + ((size_t)b * KVh + kvh) * Dh * Ssz;
    const __nv_bfloat16* vtlp = vtl + ((size_t)b * KVh + kvh) * Dh * Ssz;

    // prologue: Q into stage1 region, KV tile0 into stage0
    {
        const int r = tid >> 1, cb = (tid & 1) * 8;
        const unsigned dq = sb + FL_STAGE + r * 272 + cb * 16;
        const char* gq = (const char*)(qhp + (size_t)r * Dh) + cb * 16;
        const char* gl = (const char*)(qlp + (size_t)r * Dh) + cb * 16;
        #pragma unroll
        for (int i = 0; i < 8; ++i) {
            CP16(dq + i * 16, gq + i * 16);
            CP16(dq + 34816 + i * 16, gl + i * 16);
        }
    }
    load_kv_tile(sb, tid, khp, klp, vthp, vtlp, 0);
    CP_COMMIT();
    asm volatile("cp.async.wait_group 0;" ::: "memory");
    __syncthreads();

    // extract Q fragments to registers
    unsigned qhf[8][4], qlf[8][4];
    {
        const unsigned qB = sb + FL_STAGE + (16 * w + (lane & 15)) * 272 + (lane >> 4) * 16;
        #pragma unroll
        for (int kt = 0; kt < 8; ++kt) {
            ldsm4(qhf[kt][0], qhf[kt][1], qhf[kt][2], qhf[kt][3], qB + kt * 32);
            ldsm4(qlf[kt][0], qlf[kt][1], qlf[kt][2], qlf[kt][3], qB + 34816 + kt * 32);
        }
    }
    __syncthreads();

    float o_[16][4];
    #pragma unroll
    for (int n = 0; n < 16; ++n)
        #pragma unroll
        for (int e = 0; e < 4; ++e) o_[n][e] = 0.0f;
    float m_lo = -1e30f, m_hi = -1e30f, l_lo = 0.0f, l_hi = 0.0f;
    const int gm_lo = mBase + 16 * w + (lane >> 2);
    const int gm_hi = gm_lo + 8;

    for (int t = 0; t < ntiles; ++t) {
        if (t + 1 < ntiles) {
            load_kv_tile(sb + ((t + 1) & 1) * FL_STAGE, tid, khp, klp, vthp, vtlp,
                         (t + 1) * 64);
            CP_COMMIT();
            asm volatile("cp.async.wait_group 1;" ::: "memory");
        } else {
            asm volatile("cp.async.wait_group 0;" ::: "memory");
        }
        __syncthreads();
        const unsigned stb = sb + (t & 1) * FL_STAGE;

        // ---- QK^T (3-term split) ----
        float s_[8][4];
        #pragma unroll
        for (int j = 0; j < 8; ++j)
            #pragma unroll
            for (int e = 0; e < 4; ++e) s_[j][e] = 0.0f;

        const unsigned kB = stb + (lane & 15) * 272 + (lane >> 4) * 16;
        #pragma unroll
        for (int kt = 0; kt < 8; ++kt) {
            #pragma unroll
            for (int nt = 0; nt < 4; ++nt) {
                unsigned r0, r1, r2, r3;
                ldsm4(r0, r1, r2, r3, kB + nt * 16 * 272 + kt * 32);
                mma16816(s_[nt * 2],     qhf[kt], r0, r2);
                mma16816(s_[nt * 2 + 1], qhf[kt], r1, r3);
                mma16816(s_[nt * 2],     qlf[kt], r0, r2);
                mma16816(s_[nt * 2 + 1], qlf[kt], r1, r3);
            }
            #pragma unroll
            for (int nt = 0; nt < 4; ++nt) {
                unsigned r0, r1, r2, r3;
                ldsm4(r0, r1, r2, r3, kB + 17408 + nt * 16 * 272 + kt * 32);
                mma16816(s_[nt * 2],     qhf[kt], r0, r2);
                mma16816(s_[nt * 2 + 1], qhf[kt], r1, r3);
            }
        }

        // ---- mask (last two tiles only) + online softmax ----
        const int nBase = t * 64;
        if (t >= 2 * qi) {
            #pragma unroll
            for (int j = 0; j < 8; ++j) {
                const int gn0 = nBase + 8 * j + (lane & 3) * 2;
                if (gn0 > gm_lo)     s_[j][0] = -1e30f;
                if (gn0 + 1 > gm_lo) s_[j][1] = -1e30f;
                if (gn0 > gm_hi)     s_[j][2] = -1e30f;
                if (gn0 + 1 > gm_hi) s_[j][3] = -1e30f;
            }
        }
        float mx_lo = m_lo, mx_hi = m_hi;
        #pragma unroll
        for (int j = 0; j < 8; ++j) {
            mx_lo = fmaxf(mx_lo, fmaxf(s_[j][0], s_[j][1]));
            mx_hi = fmaxf(mx_hi, fmaxf(s_[j][2], s_[j][3]));
        }
        mx_lo = fmaxf(mx_lo, __shfl_xor_sync(0xffffffffu, mx_lo, 1));
        mx_lo = fmaxf(mx_lo, __shfl_xor_sync(0xffffffffu, mx_lo, 2));
        mx_hi = fmaxf(mx_hi, __shfl_xor_sync(0xffffffffu, mx_hi, 1));
        mx_hi = fmaxf(mx_hi, __shfl_xor_sync(0xffffffffu, mx_hi, 2));

        const float al = __expf(m_lo - mx_lo);
        const float ah = __expf(m_hi - mx_hi);
        m_lo = mx_lo; m_hi = mx_hi;

        float sl = 0.0f, sh = 0.0f;
        #pragma unroll
        for (int j = 0; j < 8; ++j) {
            float p0 = __expf(s_[j][0] - mx_lo);
            float p1 = __expf(s_[j][1] - mx_lo);
            float p2 = __expf(s_[j][2] - mx_hi);
            float p3 = __expf(s_[j][3] - mx_hi);
            s_[j][0] = p0; s_[j][1] = p1; s_[j][2] = p2; s_[j][3] = p3;
            sl += p0 + p1; sh += p2 + p3;
        }
        sl += __shfl_xor_sync(0xffffffffu, sl, 1);
        sl += __shfl_xor_sync(0xffffffffu, sl, 2);
        sh += __shfl_xor_sync(0xffffffffu, sh, 1);
        sh += __shfl_xor_sync(0xffffffffu, sh, 2);
        l_lo = l_lo * al + sl;
        l_hi = l_hi * ah + sh;
        #pragma unroll
        for (int n = 0; n < 16; ++n) {
            o_[n][0] *= al; o_[n][1] *= al;
            o_[n][2] *= ah; o_[n][3] *= ah;
        }

        // ---- PV (3-term split, P from registers) ----
        const unsigned vB = stb + 34816 + (lane & 15) * 144 + (lane >> 4) * 16;
        #pragma unroll
        for (int kt2 = 0; kt2 < 4; ++kt2) {
            const float* pa = s_[2 * kt2];
            const float* pb = s_[2 * kt2 + 1];
            unsigned ahf[4], alf[4];
            ahf[0] = pack2(pa[0], pa[1]); ahf[1] = pack2(pa[2], pa[3]);
            ahf[2] = pack2(pb[0], pb[1]); ahf[3] = pack2(pb[2], pb[3]);
            alf[0] = pack2(bfres(pa[0]), bfres(pa[1]));
            alf[1] = pack2(bfres(pa[2]), bfres(pa[3]));
            alf[2] = pack2(bfres(pb[0]), bfres(pb[1]));
            alf[3] = pack2(bfres(pb[2]), bfres(pb[3]));
            #pragma unroll
            for (int vt = 0; vt < 8; ++vt) {
                unsigned r0, r1, r2, r3;
                ldsm4(r0, r1, r2, r3, vB + vt * 16 * 144 + kt2 * 32);
                mma16816(o_[2 * vt],     ahf, r0, r2);
                mma16816(o_[2 * vt + 1], ahf, r1, r3);
                mma16816(o_[2 * vt],     alf, r0, r2);
                mma16816(o_[2 * vt + 1], alf, r1, r3);
            }
            #pragma unroll
            for (int vt = 0; vt < 8; ++vt) {
                unsigned r0, r1, r2, r3;
                ldsm4(r0, r1, r2, r3, vB + 18432 + vt * 16 * 144 + kt2 * 32);
                mma16816(o_[2 * vt],     ahf, r0, r2);
                mma16816(o_[2 * vt + 1], ahf, r1, r3);
            }
        }
        __syncthreads();
    }

    // ---- epilogue ----
    const float il = 1.0f / l_lo, ih = 1.0f / l_hi;
    float* orl = out + ((size_t)(b * Ssz + gm_lo) * Hh + h) * Dh;
    float* orh = out + ((size_t)(b * Ssz + gm_hi) * Hh + h) * Dh;
    #pragma unroll
    for (int n = 0; n < 16; ++n) {
        const int col = 8 * n + (lane & 3) * 2;
        *(float2*)(orl + col) = make_float2(o_[n][0] * il, o_[n][1] * il);
        *(float2*)(orh + col) = make_float2(o_[n][2] * ih, o_[n][3] * ih);
    }
}

// ---------------- host launch -------------------------------------------------
extern "C" void kernel_launch(void* const* d_in, const int* in_sizes, int n_in,
                              void* d_out, int out_size)
{
    const float* x   = (const float*)d_in[0];
    const float* Wq  = (const float*)d_in[1];
    const float* Wk  = (const float*)d_in[2];
    const float* Wv  = (const float*)d_in[3];
    const float* Wo  = (const float*)d_in[4];
    const float* qnw = (const float*)d_in[5];
    const float* knw = (const float*)d_in[6];
    const float* cs  = (const float*)d_in[7];
    const float* sn  = (const float*)d_in[8];

    float *qb, *kb, *vb, *ab;
    __nv_bfloat16 *xp, *ap, *wqt, *wkt, *wvt, *wot;
    __nv_bfloat16 *qhh, *qll, *khh, *kll, *vth, *vtl;
    cudaGetSymbolAddress((void**)&qb, g_q);
    cudaGetSymbolAddress((void**)&kb, g_k);
    cudaGetSymbolAddress((void**)&vb, g_v);
    cudaGetSymbolAddress((void**)&ab, g_att);
    cudaGetSymbolAddress((void**)&xp, g_xp);
    cudaGetSymbolAddress((void**)&ap, g_ap);
    cudaGetSymbolAddress((void**)&wqt, g_wqt);
    cudaGetSymbolAddress((void**)&wkt, g_wkt);
    cudaGetSymbolAddress((void**)&wvt, g_wvt);
    cudaGetSymbolAddress((void**)&wot, g_wot);
    cudaGetSymbolAddress((void**)&qhh, g_qh);
    cudaGetSymbolAddress((void**)&qll, g_ql);
    cudaGetSymbolAddress((void**)&khh, g_kh);
    cudaGetSymbolAddress((void**)&kll, g_kl);
    cudaGetSymbolAddress((void**)&vth, g_vth);
    cudaGetSymbolAddress((void**)&vtl, g_vtl);

    cudaFuncSetAttribute(gemm_mma, cudaFuncAttributeMaxDynamicSharedMemorySize, GEMM_SMEM);
    cudaFuncSetAttribute(flash_mma, cudaFuncAttributeMaxDynamicSharedMemorySize, FL_SMEM);

    // split/convert inputs + weights
    conv_a<<<8192, 256>>>(x, xp);
    conv_w<<<dim3(64, 64), 256>>>(Wq, wqt, 2048);
    conv_w<<<dim3(32, 64), 256>>>(Wk, wkt, 1024);
    conv_w<<<dim3(32, 64), 256>>>(Wv, wvt, 1024);
    conv_w<<<dim3(64, 64), 256>>>(Wo, wot, 2048);

    // QKV projections (bf16x3 HMMA)
    gemm_mma<<<dim3(16, 32), 256, GEMM_SMEM>>>(xp, wqt, qb, 2048);
    gemm_mma<<<dim3(8, 32), 256, GEMM_SMEM>>>(xp, wkt, kb, 1024);
    gemm_mma<<<dim3(8, 32), 256, GEMM_SMEM>>>(xp, wvt, vb, 1024);

    // RMSNorm + RoPE
    norm_rope_k<<<(Bsz * Ssz * Hh) / 8, 256>>>(qb, qnw, cs, sn, Hh);
    norm_rope_k<<<(Bsz * Ssz * KVh) / 8, 256>>>(kb, knw, cs, sn, KVh);

    // head-major bf16 splits for flash (Q pre-scaled by 1/sqrt(D))
    conv_qk<<<8192, 256>>>(qb, qhh, qll, Hh, 0.08838834764831845f);
    conv_qk<<<4096, 256>>>(kb, khh, kll, KVh, 1.0f);
    conv_vt<<<dim3(64, 4, 16), 256>>>(vb, vth, vtl);

    // flash attention (HMMA)
    flash_mma<<<dim3(16, Hh, Bsz), 256, FL_SMEM>>>(qhh, qll, khh, kll, vth, vtl, ab);

    // output projection
    conv_a<<<8192, 256>>>(ab, ap);
    gemm_mma<<<dim3(16, 32), 256, GEMM_SMEM>>>(ap, wot, (float*)d_out, 2048);
}